// round 12
// baseline (speedup 1.0000x reference)
#include <cuda_runtime.h>

#define HW 2304               // 48*48
#define HW4 576               // HW/4 (float4 plane stride)
#define NIMG 128              // B*N
#define PRED_I_ELEMS 884736   // 16*8*3*48*48
#define PRED_ELEMS   110592   // 16*3*48*48

__device__ float g_pred_i_scratch[PRED_I_ELEMS];
// Monotonic completion counters, one per b. Never reset: each launch adds
// exactly 8 per counter, so ((old+1)&7)==0 marks that launch's last block.
__device__ unsigned int g_done_cnt[16];

// One block per (b,n) image; exactly 1 CTA/SM (no cross-CTA L1tex contention).
// 576 threads = 48 rows x 12 quads; each thread owns one 4-pixel float4 quad.
__global__ __launch_bounds__(576, 1)
void conv_fused_kernel(const float* __restrict__ frames,
                       const float* __restrict__ core,
                       const float* __restrict__ kwt,
                       float* __restrict__ pred_i,
                       float* __restrict__ pred) {     // may be nullptr
    const int bn  = blockIdx.x;
    const int tid = threadIdx.x;

    // channel-summed, zero-padded frame tile: fsum[(y+2)*52 + (x+2)]
    __shared__ float fsum[52 * 52];
    {
        const float* fr = frames + (size_t)bn * 3 * HW;
        for (int i = tid; i < 52 * 52; i += 576) {
            int yy = i / 52 - 2;
            int xx = i % 52 - 2;
            float v = 0.f;
            if ((unsigned)yy < 48u && (unsigned)xx < 48u) {
                int p = yy * 48 + xx;
                v = fr[p] + fr[HW + p] + fr[2 * HW + p];
            }
            fsum[i] = v;
        }
    }
    __syncthreads();

    const float* cb = core + (size_t)bn * 300 * HW;  // [300,H,W] planes
    const float* kb = kwt  + (size_t)bn * 12  * HW;  // [4,3,H,W] planes
    float*       ob = pred_i + (size_t)bn * 3 * HW;

    const int xb   = (tid % 12) * 4;
    const int y    = tid / 12;                       // 0..47
    const int pixq = y * 48 + xb;                    // 16B-aligned quad start

    // 5x8 window of shifted frame-sums covering this thread's 4 pixels
    float win[5][8];
    #pragma unroll
    for (int i = 0; i < 5; ++i)
        #pragma unroll
        for (int j = 0; j < 8; ++j)
            win[i][j] = fsum[(y + i) * 52 + xb + j];

    float4 a0 = {0,0,0,0}, a1 = {0,0,0,0}, a2 = {0,0,0,0};

    #pragma unroll
    for (int g = 0; g < 4; ++g) {
        // pk[g,k,c] lives at core mid-index m = g*75 + 3k + c
        const float4* cg = (const float4*)(cb + (size_t)(g * 75) * HW + pixq);
        float4 s0 = {0,0,0,0}, s1 = {0,0,0,0}, s2 = {0,0,0,0};
        #pragma unroll
        for (int k = 0; k < 25; ++k) {
            const int i = k / 5, j = k % 5;
            const float4 c0 = cg[(3 * k + 0) * HW4];
            const float4 c1 = cg[(3 * k + 1) * HW4];
            const float4 c2 = cg[(3 * k + 2) * HW4];
            s0.x = fmaf(win[i][j+0], c0.x, s0.x);
            s0.y = fmaf(win[i][j+1], c0.y, s0.y);
            s0.z = fmaf(win[i][j+2], c0.z, s0.z);
            s0.w = fmaf(win[i][j+3], c0.w, s0.w);
            s1.x = fmaf(win[i][j+0], c1.x, s1.x);
            s1.y = fmaf(win[i][j+1], c1.y, s1.y);
            s1.z = fmaf(win[i][j+2], c1.z, s1.z);
            s1.w = fmaf(win[i][j+3], c1.w, s1.w);
            s2.x = fmaf(win[i][j+0], c2.x, s2.x);
            s2.y = fmaf(win[i][j+1], c2.y, s2.y);
            s2.z = fmaf(win[i][j+2], c2.z, s2.z);
            s2.w = fmaf(win[i][j+3], c2.w, s2.w);
        }
        const float4* kg = (const float4*)(kb + pixq);
        const float4 w0 = kg[(g * 3 + 0) * HW4];
        const float4 w1 = kg[(g * 3 + 1) * HW4];
        const float4 w2 = kg[(g * 3 + 2) * HW4];
        a0.x = fmaf(w0.x, s0.x, a0.x); a0.y = fmaf(w0.y, s0.y, a0.y);
        a0.z = fmaf(w0.z, s0.z, a0.z); a0.w = fmaf(w0.w, s0.w, a0.w);
        a1.x = fmaf(w1.x, s1.x, a1.x); a1.y = fmaf(w1.y, s1.y, a1.y);
        a1.z = fmaf(w1.z, s1.z, a1.z); a1.w = fmaf(w1.w, s1.w, a1.w);
        a2.x = fmaf(w2.x, s2.x, a2.x); a2.y = fmaf(w2.y, s2.y, a2.y);
        a2.z = fmaf(w2.z, s2.z, a2.z); a2.w = fmaf(w2.w, s2.w, a2.w);
    }

    float4* o4 = (float4*)(ob + pixq);
    o4[0]       = make_float4(0.25f*a0.x, 0.25f*a0.y, 0.25f*a0.z, 0.25f*a0.w);
    o4[HW4]     = make_float4(0.25f*a1.x, 0.25f*a1.y, 0.25f*a1.z, 0.25f*a1.w);
    o4[2 * HW4] = make_float4(0.25f*a2.x, 0.25f*a2.y, 0.25f*a2.z, 0.25f*a2.w);

    if (pred == nullptr) return;

    // ---- fused mean-over-n: last finished of the 8 blocks of this b reduces.
    // Its inputs (8 x 221KB slabs) were just written -> L2-resident; runs on
    // one SM per b while other SMs still stream DRAM.
    const int b = bn >> 3;
    __shared__ unsigned int s_last;
    __threadfence();                          // publish pred_i writes
    __syncthreads();
    if (tid == 0) {
        unsigned int old = atomicAdd(&g_done_cnt[b], 1u);
        s_last = (((old + 1u) & 7u) == 0u);
    }
    __syncthreads();
    if (!s_last) return;
    __threadfence();                          // acquire: see peers' pred_i writes

    const int perb = 3 * HW4;                 // 1728 quads per (c,h,w) slab
    const float4* pbase = (const float4*)pred_i + (size_t)b * 8 * perb;
    float4* pout = (float4*)pred + (size_t)b * perb;
    #pragma unroll 1
    for (int r = tid; r < perb; r += 576) {
        float4 s = {0,0,0,0};
        #pragma unroll
        for (int n = 0; n < 8; ++n) {
            float4 v = __ldcg(&pbase[(size_t)n * perb + r]);
            s.x += v.x; s.y += v.y; s.z += v.z; s.w += v.w;
        }
        s.x *= 0.125f; s.y *= 0.125f; s.z *= 0.125f; s.w *= 0.125f;
        pout[r] = s;
    }
}

extern "C" void kernel_launch(void* const* d_in, const int* in_sizes, int n_in,
                              void* d_out, int out_size) {
    const float* frames = (const float*)d_in[0];
    const float* core   = (const float*)d_in[1];
    const float* kwt    = (const float*)d_in[2];
    float* out = (float*)d_out;

    if (out_size >= PRED_I_ELEMS + PRED_ELEMS) {
        conv_fused_kernel<<<NIMG, 576>>>(frames, core, kwt,
                                         out, out + PRED_I_ELEMS);
    } else if (out_size >= PRED_I_ELEMS) {
        conv_fused_kernel<<<NIMG, 576>>>(frames, core, kwt, out, nullptr);
    } else {
        conv_fused_kernel<<<NIMG, 576>>>(frames, core, kwt,
                                         g_pred_i_scratch, out);
    }
}

// round 13
// speedup vs baseline: 1.0209x; 1.0209x over previous
#include <cuda_runtime.h>

#define HW 2304               // 48*48
#define HW4 576               // HW/4 (float4 plane stride)
#define NIMG 128              // B*N
#define PRED_I_ELEMS 884736   // 16*8*3*48*48
#define PRED_ELEMS   110592   // 16*3*48*48

__device__ float g_pred_i_scratch[PRED_I_ELEMS];

// Zero pred so conv blocks can REDG-accumulate the mean into it.
__global__ __launch_bounds__(128)
void zero_pred_kernel(float* __restrict__ pred) {
    int idx = blockIdx.x * blockDim.x + threadIdx.x;
    if (idx < PRED_ELEMS / 4)
        ((float4*)pred)[idx] = make_float4(0.f, 0.f, 0.f, 0.f);
}

// One block per (b,n) image; exactly 1 CTA/SM (no cross-CTA L1tex contention).
// 576 threads = 48 rows x 12 quads; each thread owns one 4-pixel float4 quad.
// pred accumulated via fire-and-forget float atomics (REDG), overlapped with
// the DRAM stream; pred region (442KB, 8-way reuse) stays L2-resident.
__global__ __launch_bounds__(576, 1)
void conv_fused_kernel(const float* __restrict__ frames,
                       const float* __restrict__ core,
                       const float* __restrict__ kwt,
                       float* __restrict__ pred_i,
                       float* __restrict__ pred) {     // may be nullptr
    const int bn  = blockIdx.x;
    const int tid = threadIdx.x;

    // channel-summed, zero-padded frame tile: fsum[(y+2)*52 + (x+2)]
    __shared__ float fsum[52 * 52];
    {
        const float* fr = frames + (size_t)bn * 3 * HW;
        for (int i = tid; i < 52 * 52; i += 576) {
            int yy = i / 52 - 2;
            int xx = i % 52 - 2;
            float v = 0.f;
            if ((unsigned)yy < 48u && (unsigned)xx < 48u) {
                int p = yy * 48 + xx;
                v = fr[p] + fr[HW + p] + fr[2 * HW + p];
            }
            fsum[i] = v;
        }
    }
    __syncthreads();

    const float* cb = core + (size_t)bn * 300 * HW;  // [300,H,W] planes
    const float* kb = kwt  + (size_t)bn * 12  * HW;  // [4,3,H,W] planes
    float*       ob = pred_i + (size_t)bn * 3 * HW;

    const int xb   = (tid % 12) * 4;
    const int y    = tid / 12;                       // 0..47
    const int pixq = y * 48 + xb;                    // 16B-aligned quad start

    // 5x8 window of shifted frame-sums covering this thread's 4 pixels
    float win[5][8];
    #pragma unroll
    for (int i = 0; i < 5; ++i)
        #pragma unroll
        for (int j = 0; j < 8; ++j)
            win[i][j] = fsum[(y + i) * 52 + xb + j];

    float4 a0 = {0,0,0,0}, a1 = {0,0,0,0}, a2 = {0,0,0,0};

    #pragma unroll
    for (int g = 0; g < 4; ++g) {
        // pk[g,k,c] lives at core mid-index m = g*75 + 3k + c
        const float4* cg = (const float4*)(cb + (size_t)(g * 75) * HW + pixq);
        float4 s0 = {0,0,0,0}, s1 = {0,0,0,0}, s2 = {0,0,0,0};
        #pragma unroll
        for (int k = 0; k < 25; ++k) {
            const int i = k / 5, j = k % 5;
            const float4 c0 = cg[(3 * k + 0) * HW4];
            const float4 c1 = cg[(3 * k + 1) * HW4];
            const float4 c2 = cg[(3 * k + 2) * HW4];
            s0.x = fmaf(win[i][j+0], c0.x, s0.x);
            s0.y = fmaf(win[i][j+1], c0.y, s0.y);
            s0.z = fmaf(win[i][j+2], c0.z, s0.z);
            s0.w = fmaf(win[i][j+3], c0.w, s0.w);
            s1.x = fmaf(win[i][j+0], c1.x, s1.x);
            s1.y = fmaf(win[i][j+1], c1.y, s1.y);
            s1.z = fmaf(win[i][j+2], c1.z, s1.z);
            s1.w = fmaf(win[i][j+3], c1.w, s1.w);
            s2.x = fmaf(win[i][j+0], c2.x, s2.x);
            s2.y = fmaf(win[i][j+1], c2.y, s2.y);
            s2.z = fmaf(win[i][j+2], c2.z, s2.z);
            s2.w = fmaf(win[i][j+3], c2.w, s2.w);
        }
        const float4* kg = (const float4*)(kb + pixq);
        const float4 w0 = kg[(g * 3 + 0) * HW4];
        const float4 w1 = kg[(g * 3 + 1) * HW4];
        const float4 w2 = kg[(g * 3 + 2) * HW4];
        a0.x = fmaf(w0.x, s0.x, a0.x); a0.y = fmaf(w0.y, s0.y, a0.y);
        a0.z = fmaf(w0.z, s0.z, a0.z); a0.w = fmaf(w0.w, s0.w, a0.w);
        a1.x = fmaf(w1.x, s1.x, a1.x); a1.y = fmaf(w1.y, s1.y, a1.y);
        a1.z = fmaf(w1.z, s1.z, a1.z); a1.w = fmaf(w1.w, s1.w, a1.w);
        a2.x = fmaf(w2.x, s2.x, a2.x); a2.y = fmaf(w2.y, s2.y, a2.y);
        a2.z = fmaf(w2.z, s2.z, a2.z); a2.w = fmaf(w2.w, s2.w, a2.w);
    }

    float4* o4 = (float4*)(ob + pixq);
    o4[0]       = make_float4(0.25f*a0.x, 0.25f*a0.y, 0.25f*a0.z, 0.25f*a0.w);
    o4[HW4]     = make_float4(0.25f*a1.x, 0.25f*a1.y, 0.25f*a1.z, 0.25f*a1.w);
    o4[2 * HW4] = make_float4(0.25f*a2.x, 0.25f*a2.y, 0.25f*a2.z, 0.25f*a2.w);

    if (pred == nullptr) return;

    // mean contribution: (1/4 over g) * (1/8 over n) = 1/32. Fire-and-forget
    // REDG.F32 (return unused); addresses spread, 8-way n-reuse lives in L2.
    const float sc = 0.03125f;
    float* pb = pred + (size_t)(bn >> 3) * 3 * HW + pixq;
    atomicAdd(&pb[0],          sc * a0.x);
    atomicAdd(&pb[1],          sc * a0.y);
    atomicAdd(&pb[2],          sc * a0.z);
    atomicAdd(&pb[3],          sc * a0.w);
    atomicAdd(&pb[HW + 0],     sc * a1.x);
    atomicAdd(&pb[HW + 1],     sc * a1.y);
    atomicAdd(&pb[HW + 2],     sc * a1.z);
    atomicAdd(&pb[HW + 3],     sc * a1.w);
    atomicAdd(&pb[2 * HW + 0], sc * a2.x);
    atomicAdd(&pb[2 * HW + 1], sc * a2.y);
    atomicAdd(&pb[2 * HW + 2], sc * a2.z);
    atomicAdd(&pb[2 * HW + 3], sc * a2.w);
}

extern "C" void kernel_launch(void* const* d_in, const int* in_sizes, int n_in,
                              void* d_out, int out_size) {
    const float* frames = (const float*)d_in[0];
    const float* core   = (const float*)d_in[1];
    const float* kwt    = (const float*)d_in[2];
    float* out = (float*)d_out;

    const int zb = (PRED_ELEMS / 4 + 127) / 128;     // 216 blocks

    if (out_size >= PRED_I_ELEMS + PRED_ELEMS) {
        float* pred = out + PRED_I_ELEMS;
        zero_pred_kernel<<<zb, 128>>>(pred);
        conv_fused_kernel<<<NIMG, 576>>>(frames, core, kwt, out, pred);
    } else if (out_size >= PRED_I_ELEMS) {
        conv_fused_kernel<<<NIMG, 576>>>(frames, core, kwt, out, nullptr);
    } else {
        zero_pred_kernel<<<zb, 128>>>(out);
        conv_fused_kernel<<<NIMG, 576>>>(frames, core, kwt,
                                         g_pred_i_scratch, out);
    }
}

// round 14
// speedup vs baseline: 1.0589x; 1.0372x over previous
#include <cuda_runtime.h>

#define HW 2304               // 48*48
#define HW4 576               // HW/4 (float4 plane stride)
#define PRED_I_ELEMS 884736   // 16*8*3*48*48
#define PRED_ELEMS   110592   // 16*3*48*48
#define RPB 42                // rows per block
#define NBLK 147              // ceil(6144/42): 146 full + 1x12-row straggler
#define THREADS 504           // 42 rows x 12 quads

__device__ float g_pred_i_scratch[PRED_I_ELEMS];

// Zero pred so conv blocks can REDG-accumulate the mean into it.
__global__ __launch_bounds__(128)
void zero_pred_kernel(float* __restrict__ pred) {
    int idx = blockIdx.x * blockDim.x + threadIdx.x;
    if (idx < PRED_ELEMS / 4)
        ((float4*)pred)[idx] = make_float4(0.f, 0.f, 0.f, 0.f);
}

// 147 blocks, strictly 1 CTA/SM (96 regs x 504 thr forbids 2). Each block owns a
// contiguous strip of 42 global rows (global row R = bn*48 + y), spanning <=2 images.
__global__ __launch_bounds__(THREADS, 1)
void conv_fused_kernel(const float* __restrict__ frames,
                       const float* __restrict__ core,
                       const float* __restrict__ kwt,
                       float* __restrict__ pred_i,
                       float* __restrict__ pred) {     // may be nullptr
    const int tid = threadIdx.x;
    const int R0  = blockIdx.x * RPB;
    const int nrows = min(RPB, 6144 - R0);

    const int bnA = R0 / 48;
    const int yA  = R0 - bnA * 48;
    const int nA  = min(48 - yA, nrows);
    const int nB  = nrows - nA;                        // rows in image bnA+1

    // two padded channel-summed frame segments (52 cols; +-2 row halo each)
    __shared__ float fsA[46 * 52];
    __shared__ float fsB[45 * 52];
    {
        const float* frA = frames + (size_t)bnA * 3 * HW;
        const int cntA = (nA + 4) * 52;
        for (int i = tid; i < cntA; i += THREADS) {
            int yy = yA - 2 + i / 52;
            int xx = i % 52 - 2;
            float v = 0.f;
            if ((unsigned)yy < 48u && (unsigned)xx < 48u) {
                int p = yy * 48 + xx;
                v = frA[p] + frA[HW + p] + frA[2 * HW + p];
            }
            fsA[i] = v;
        }
        if (nB > 0) {
            const float* frB = frames + (size_t)(bnA + 1) * 3 * HW;
            const int cntB = (nB + 4) * 52;
            for (int i = tid; i < cntB; i += THREADS) {
                int yy = -2 + i / 52;
                int xx = i % 52 - 2;
                float v = 0.f;
                if ((unsigned)yy < 48u && (unsigned)xx < 48u) {
                    int p = yy * 48 + xx;
                    v = frB[p] + frB[HW + p] + frB[2 * HW + p];
                }
                fsB[i] = v;
            }
        }
    }
    __syncthreads();

    const int q = tid % 12;
    const int l = tid / 12;                            // local strip row 0..41
    if (l >= nrows) return;                            // straggler block only

    const bool inA = (l < nA);
    const int  bn  = inA ? bnA : (bnA + 1);
    const int  y   = inA ? (yA + l) : (l - nA);
    const float* fbase = inA ? (fsA + l * 52) : (fsB + (l - nA) * 52);

    const int xb   = q * 4;
    const int pixq = y * 48 + xb;                      // 16B-aligned quad start

    const float* cb = core + (size_t)bn * 300 * HW;    // [300,H,W] planes
    const float* kb = kwt  + (size_t)bn * 12  * HW;
    float*       ob = pred_i + (size_t)bn * 3 * HW;

    // 5x8 window of shifted frame-sums covering this thread's 4 pixels
    float win[5][8];
    #pragma unroll
    for (int i = 0; i < 5; ++i)
        #pragma unroll
        for (int j = 0; j < 8; ++j)
            win[i][j] = fbase[i * 52 + xb + j];

    float4 a0 = {0,0,0,0}, a1 = {0,0,0,0}, a2 = {0,0,0,0};

    #pragma unroll
    for (int g = 0; g < 4; ++g) {
        // pk[g,k,c] lives at core mid-index m = g*75 + 3k + c
        const float4* cg = (const float4*)(cb + (size_t)(g * 75) * HW + pixq);
        float4 s0 = {0,0,0,0}, s1 = {0,0,0,0}, s2 = {0,0,0,0};
        #pragma unroll
        for (int k = 0; k < 25; ++k) {
            const int i = k / 5, j = k % 5;
            const float4 c0 = cg[(3 * k + 0) * HW4];
            const float4 c1 = cg[(3 * k + 1) * HW4];
            const float4 c2 = cg[(3 * k + 2) * HW4];
            s0.x = fmaf(win[i][j+0], c0.x, s0.x);
            s0.y = fmaf(win[i][j+1], c0.y, s0.y);
            s0.z = fmaf(win[i][j+2], c0.z, s0.z);
            s0.w = fmaf(win[i][j+3], c0.w, s0.w);
            s1.x = fmaf(win[i][j+0], c1.x, s1.x);
            s1.y = fmaf(win[i][j+1], c1.y, s1.y);
            s1.z = fmaf(win[i][j+2], c1.z, s1.z);
            s1.w = fmaf(win[i][j+3], c1.w, s1.w);
            s2.x = fmaf(win[i][j+0], c2.x, s2.x);
            s2.y = fmaf(win[i][j+1], c2.y, s2.y);
            s2.z = fmaf(win[i][j+2], c2.z, s2.z);
            s2.w = fmaf(win[i][j+3], c2.w, s2.w);
        }
        const float4* kg = (const float4*)(kb + pixq);
        const float4 w0 = kg[(g * 3 + 0) * HW4];
        const float4 w1 = kg[(g * 3 + 1) * HW4];
        const float4 w2 = kg[(g * 3 + 2) * HW4];
        a0.x = fmaf(w0.x, s0.x, a0.x); a0.y = fmaf(w0.y, s0.y, a0.y);
        a0.z = fmaf(w0.z, s0.z, a0.z); a0.w = fmaf(w0.w, s0.w, a0.w);
        a1.x = fmaf(w1.x, s1.x, a1.x); a1.y = fmaf(w1.y, s1.y, a1.y);
        a1.z = fmaf(w1.z, s1.z, a1.z); a1.w = fmaf(w1.w, s1.w, a1.w);
        a2.x = fmaf(w2.x, s2.x, a2.x); a2.y = fmaf(w2.y, s2.y, a2.y);
        a2.z = fmaf(w2.z, s2.z, a2.z); a2.w = fmaf(w2.w, s2.w, a2.w);
    }

    float4* o4 = (float4*)(ob + pixq);
    o4[0]       = make_float4(0.25f*a0.x, 0.25f*a0.y, 0.25f*a0.z, 0.25f*a0.w);
    o4[HW4]     = make_float4(0.25f*a1.x, 0.25f*a1.y, 0.25f*a1.z, 0.25f*a1.w);
    o4[2 * HW4] = make_float4(0.25f*a2.x, 0.25f*a2.y, 0.25f*a2.z, 0.25f*a2.w);

    if (pred == nullptr) return;

    // mean contribution: (1/4 over g)*(1/8 over n) = 1/32; fire-and-forget REDG.
    const float sc = 0.03125f;
    float* pb = pred + (size_t)(bn >> 3) * 3 * HW + pixq;
    atomicAdd(&pb[0],          sc * a0.x);
    atomicAdd(&pb[1],          sc * a0.y);
    atomicAdd(&pb[2],          sc * a0.z);
    atomicAdd(&pb[3],          sc * a0.w);
    atomicAdd(&pb[HW + 0],     sc * a1.x);
    atomicAdd(&pb[HW + 1],     sc * a1.y);
    atomicAdd(&pb[HW + 2],     sc * a1.z);
    atomicAdd(&pb[HW + 3],     sc * a1.w);
    atomicAdd(&pb[2 * HW + 0], sc * a2.x);
    atomicAdd(&pb[2 * HW + 1], sc * a2.y);
    atomicAdd(&pb[2 * HW + 2], sc * a2.z);
    atomicAdd(&pb[2 * HW + 3], sc * a2.w);
}

extern "C" void kernel_launch(void* const* d_in, const int* in_sizes, int n_in,
                              void* d_out, int out_size) {
    const float* frames = (const float*)d_in[0];
    const float* core   = (const float*)d_in[1];
    const float* kwt    = (const float*)d_in[2];
    float* out = (float*)d_out;

    const int zb = (PRED_ELEMS / 4 + 127) / 128;     // 216 blocks

    if (out_size >= PRED_I_ELEMS + PRED_ELEMS) {
        float* pred = out + PRED_I_ELEMS;
        zero_pred_kernel<<<zb, 128>>>(pred);
        conv_fused_kernel<<<NBLK, THREADS>>>(frames, core, kwt, out, pred);
    } else if (out_size >= PRED_I_ELEMS) {
        conv_fused_kernel<<<NBLK, THREADS>>>(frames, core, kwt, out, nullptr);
    } else {
        zero_pred_kernel<<<zb, 128>>>(out);
        conv_fused_kernel<<<NBLK, THREADS>>>(frames, core, kwt,
                                             g_pred_i_scratch, out);
    }
}